// round 1
// baseline (speedup 1.0000x reference)
#include <cuda_runtime.h>

// BakeAugment: the JPEG stage at quality=15 quantizes every DCT coefficient to
// zero (|dctp/q| <= 8/33.3 < 0.5 with margin), so apply_jpeg() is the constant
// image (0, 0.34414*0.5+0.71414*0.5, 0). The whole reference collapses to two
// elementwise streams:
//   inp    = clip( clip(Cc + gauss*0.03, 0,1) + sh_c, 1e-8,1)^0.9  (clip 0..1)
//   target = clip( clip(x + sh_c,          1e-8,1)^0.9, 0,1)
// where sh_c = shift[c]*0.05 and Cc = (0, 0.52914, 0).
//
// Memory-bound: 201 MB of HBM traffic -> ~30 us floor on GB300.

__device__ __forceinline__ float gamma_clip(float v) {
    v = fminf(fmaxf(v, 1e-8f), 1.0f);
    v = powf(v, 0.9f);
    return fminf(fmaxf(v, 0.0f), 1.0f);
}

__global__ void __launch_bounds__(256)
bake_kernel(const float* __restrict__ x,
            const float* __restrict__ gauss,
            const float* __restrict__ shift,
            float* __restrict__ out,
            int n4)  // number of float4 elements per output tensor
{
    int q = blockIdx.x * blockDim.x + threadIdx.x;
    if (q >= n4) return;

    // H*W = 512*512 = 262144 floats = 65536 float4 per channel image.
    // channel index = (q >> 16) % 3
    int c = (q >> 16) % 3;
    // apply_jpeg constant output per channel (computed exactly as reference):
    // y=0, cb-0.5=-0.5, cr-0.5=-0.5 ->
    //   r = 1.402*(-0.5) -> clip 0
    //   g = -0.34414*(-0.5) - 0.71414*(-0.5) = 0.52914
    //   b = 1.772*(-0.5) -> clip 0
    float cc = (c == 1) ? (0.34414f * 0.5f + 0.71414f * 0.5f) : 0.0f;
    float sh = __ldg(&shift[c]) * 0.05f;

    float4 g4 = reinterpret_cast<const float4*>(gauss)[q];
    float4 x4 = reinterpret_cast<const float4*>(x)[q];

    float4 o_inp, o_tgt;

    // inp path: clip(const + gauss*SIGMA, 0,1) + sh, then gamma
    o_inp.x = gamma_clip(fminf(fmaxf(cc + g4.x * 0.03f, 0.0f), 1.0f) + sh);
    o_inp.y = gamma_clip(fminf(fmaxf(cc + g4.y * 0.03f, 0.0f), 1.0f) + sh);
    o_inp.z = gamma_clip(fminf(fmaxf(cc + g4.z * 0.03f, 0.0f), 1.0f) + sh);
    o_inp.w = gamma_clip(fminf(fmaxf(cc + g4.w * 0.03f, 0.0f), 1.0f) + sh);

    // target path: x + sh, then gamma
    o_tgt.x = gamma_clip(x4.x + sh);
    o_tgt.y = gamma_clip(x4.y + sh);
    o_tgt.z = gamma_clip(x4.z + sh);
    o_tgt.w = gamma_clip(x4.w + sh);

    reinterpret_cast<float4*>(out)[q]      = o_inp;
    reinterpret_cast<float4*>(out)[q + n4] = o_tgt;
}

extern "C" void kernel_launch(void* const* d_in, const int* in_sizes, int n_in,
                              void* d_out, int out_size) {
    // Inputs per setup_inputs() order: x, dither, gauss, shift
    const float* x     = (const float*)d_in[0];
    // d_in[1] (dither) is mathematically unused: the JPEG stage is constant.
    const float* gauss = (const float*)d_in[2];
    const float* shift = (const float*)d_in[3];
    float* out = (float*)d_out;

    int n  = out_size / 2;   // elements per output tensor (inp, target)
    int n4 = n / 4;          // float4 count (H*W divisible by 4)

    int threads = 256;
    int blocks = (n4 + threads - 1) / threads;
    bake_kernel<<<blocks, threads>>>(x, gauss, shift, out, n4);
}

// round 2
// speedup vs baseline: 1.7625x; 1.7625x over previous
#include <cuda_runtime.h>

// BakeAugment: the JPEG stage at quality=15 quantizes every DCT coefficient to
// zero (|dctp/q| <= 8/33.3 < 0.5 with margin), so apply_jpeg() is the constant
// image (0, 0.34414*0.5+0.71414*0.5, 0). The reference collapses to two
// elementwise streams:
//   inp    = clip( clip(Cc + gauss*0.03, 0,1) + sh_c, 1e-8,1)^0.9  (clip 0..1)
//   target = clip( clip(x + sh_c,          1e-8,1)^0.9, 0,1)
// where sh_c = shift[c]*0.05 and Cc = (0, 0.52914, 0).
//
// R1 lesson: full-precision powf() saturated fma/alu pipes (50%/50%, DRAM 33%).
// Use MUFU fast path (LG2 + FMUL + EX2): pow rel-err ~1.5e-7 << 1e-3 budget.
// Memory-bound floor: 201 MB HBM traffic -> ~31 us on GB300.

__device__ __forceinline__ float gamma_clip(float v) {
    v = fminf(fmaxf(v, 1e-8f), 1.0f);
    // v in [1e-8, 1] -> pow(v, 0.9) via MUFU.LG2 / MUFU.EX2
    v = exp2f(0.9f * __log2f(v));
    return fminf(v, 1.0f);   // result >= 0 by construction; only top clip needed
}

__global__ void __launch_bounds__(256)
bake_kernel(const float* __restrict__ x,
            const float* __restrict__ gauss,
            const float* __restrict__ shift,
            float* __restrict__ out,
            int n4)  // float4 elements per output tensor
{
    int q = blockIdx.x * blockDim.x + threadIdx.x;
    if (q >= n4) return;

    // H*W = 512*512 floats = 65536 float4 per channel image.
    int c = (q >> 16) % 3;
    // apply_jpeg constant per channel: (0, 0.34414*0.5 + 0.71414*0.5, 0)
    float cc = (c == 1) ? (0.34414f * 0.5f + 0.71414f * 0.5f) : 0.0f;
    float sh = __ldg(&shift[c]) * 0.05f;

    float4 g4 = reinterpret_cast<const float4*>(gauss)[q];
    float4 x4 = reinterpret_cast<const float4*>(x)[q];

    float4 o_inp, o_tgt;

    // inp path: clip(const + gauss*SIGMA, 0,1) + sh, then gamma
    o_inp.x = gamma_clip(fminf(fmaxf(fmaf(g4.x, 0.03f, cc), 0.0f), 1.0f) + sh);
    o_inp.y = gamma_clip(fminf(fmaxf(fmaf(g4.y, 0.03f, cc), 0.0f), 1.0f) + sh);
    o_inp.z = gamma_clip(fminf(fmaxf(fmaf(g4.z, 0.03f, cc), 0.0f), 1.0f) + sh);
    o_inp.w = gamma_clip(fminf(fmaxf(fmaf(g4.w, 0.03f, cc), 0.0f), 1.0f) + sh);

    // target path: x + sh, then gamma
    o_tgt.x = gamma_clip(x4.x + sh);
    o_tgt.y = gamma_clip(x4.y + sh);
    o_tgt.z = gamma_clip(x4.z + sh);
    o_tgt.w = gamma_clip(x4.w + sh);

    reinterpret_cast<float4*>(out)[q]      = o_inp;
    reinterpret_cast<float4*>(out)[q + n4] = o_tgt;
}

extern "C" void kernel_launch(void* const* d_in, const int* in_sizes, int n_in,
                              void* d_out, int out_size) {
    // Inputs per setup_inputs() order: x, dither, gauss, shift
    const float* x     = (const float*)d_in[0];
    // d_in[1] (dither) is mathematically unused: the JPEG stage is constant.
    const float* gauss = (const float*)d_in[2];
    const float* shift = (const float*)d_in[3];
    float* out = (float*)d_out;

    int n  = out_size / 2;   // elements per output tensor (inp, target)
    int n4 = n / 4;

    int threads = 256;
    int blocks = (n4 + threads - 1) / threads;
    bake_kernel<<<blocks, threads>>>(x, gauss, shift, out, n4);
}